// round 10
// baseline (speedup 1.0000x reference)
#include <cuda_runtime.h>
#include <cuda_bf16.h>
#include <cstdint>
#include <cstddef>

#define NN 50000
#define NE 600000
#define D 128
#define BN_EPS 1e-5f

// ---------------- scratch (device globals) -------------------------------------
__device__ float g_h[NN * D];                 // post-BN node features (fp32)
__device__ __nv_bfloat16 g_agg_hi[NN * D];    // aggregate, bf16 split
__device__ __nv_bfloat16 g_agg_lo[NN * D];
__device__ float g_h2[NN * D];                // pre-BN layer output (fp32)
__device__ float g_sum[D];
__device__ float g_sumsq[D];
__device__ float g_bns[D];
__device__ float g_bnt[D];
// pre-split transposed weights
__device__ __nv_bfloat16 g_wt1_hi[5 * 256 * 128];
__device__ __nv_bfloat16 g_wt1_lo[5 * 256 * 128];
__device__ __nv_bfloat16 g_wt2_hi[5 * 128 * 256];
__device__ __nv_bfloat16 g_wt2_lo[5 * 128 * 256];
// CSR structures
__device__ int   g_cnt[NN];
__device__ int   g_rowstart[NN + 1];
__device__ int   g_cursor[NN];
__device__ int   g_edges[NE];                 // src | (combo << 16)
__device__ float g_eec[5 * 24 * D];           // all layers precomputed

// ---------------- helpers -------------------------------------------------------
__device__ __forceinline__ uint32_t pack2bf(float x, float y) {
    __nv_bfloat162 h = __floats2bfloat162_rn(x, y);
    return *(uint32_t*)&h;
}
__device__ __forceinline__ void split2(float x, float y,
                                       uint32_t& hi, uint32_t& lo) {
    __nv_bfloat16 hx = __float2bfloat16(x);
    __nv_bfloat16 hy = __float2bfloat16(y);
    float rx = x - __bfloat162float(hx);
    float ry = y - __bfloat162float(hy);
    __nv_bfloat162 h2 = __halves2bfloat162(hx, hy);
    hi = *(uint32_t*)&h2;
    lo = pack2bf(rx, ry);
}
__device__ __forceinline__ void cp_async16(void* dst, const void* src,
                                           int src_bytes) {
    uint32_t d = (uint32_t)__cvta_generic_to_shared(dst);
    asm volatile("cp.async.cg.shared.global [%0], [%1], 16, %2;\n"
                 :: "r"(d), "l"(src), "r"(src_bytes));
}
#define CP_COMMIT() asm volatile("cp.async.commit_group;\n" ::: "memory")
#define CP_WAIT(n)  asm volatile("cp.async.wait_group %0;\n" :: "n"(n) : "memory")

// ---------------- input embedding ---------------------------------------------
__global__ void embed_kernel(const int* __restrict__ x,
                             const float* __restrict__ atom,
                             const float* __restrict__ chir,
                             const float* __restrict__ hyb) {
    int t = blockIdx.x * blockDim.x + threadIdx.x;
    int node = t >> 5, lane = t & 31;
    if (node >= NN) return;
    int x0 = x[node * 3 + 0];
    int x1 = x[node * 3 + 1];
    int x2 = x[node * 3 + 2];
    float4 a = ((const float4*)(atom + (size_t)x0 * D))[lane];
    float4 c = ((const float4*)(chir + (size_t)x1 * D))[lane];
    float4 y = ((const float4*)(hyb  + (size_t)x2 * D))[lane];
    ((float4*)g_h)[(size_t)node * 32 + lane] =
        make_float4(a.x + c.x + y.x, a.y + c.y + y.y,
                    a.z + c.z + y.z, a.w + c.w + y.w);
}

// ---------------- weight prep: transpose + bf16 split --------------------------
__global__ void wprep_kernel(const float* __restrict__ W1,
                             const float* __restrict__ W2) {
    int t = blockIdx.x * blockDim.x + threadIdx.x;
    int total = 5 * 128 * 256;
    if (t < total) {
        int l = t / (128 * 256);
        int r = t % (128 * 256);
        int k = r / 256, n = r % 256;
        float v = W1[t];
        __nv_bfloat16 h = __float2bfloat16(v);
        g_wt1_hi[l * 32768 + n * 128 + k] = h;
        g_wt1_lo[l * 32768 + n * 128 + k] =
            __float2bfloat16(v - __bfloat162float(h));
    } else if (t < 2 * total) {
        int u = t - total;
        int l = u / (256 * 128);
        int r = u % (256 * 128);
        int k = r / 128, n = r % 128;
        float v = W2[u];
        __nv_bfloat16 h = __float2bfloat16(v);
        g_wt2_hi[l * 32768 + n * 256 + k] = h;
        g_wt2_lo[l * 32768 + n * 256 + k] =
            __float2bfloat16(v - __bfloat162float(h));
    }
}

// ---------------- CSR build ----------------------------------------------------
__global__ void count_kernel(const int* __restrict__ ei) {
    int e = blockIdx.x * blockDim.x + threadIdx.x;
    if (e >= NE) return;
    atomicAdd(&g_cnt[ei[NE + e]], 1);
}

__global__ void scan_kernel() {
    __shared__ int warpsum[32];
    __shared__ int carry;
    int lane = threadIdx.x & 31, wid = threadIdx.x >> 5;
    if (threadIdx.x == 0) carry = 0;
    __syncthreads();
    for (int base = 0; base < NN; base += 1024) {
        int i = base + threadIdx.x;
        int v = (i < NN) ? g_cnt[i] : 0;
        int xs = v;
#pragma unroll
        for (int off = 1; off < 32; off <<= 1) {
            int t = __shfl_up_sync(0xffffffff, xs, off);
            if (lane >= off) xs += t;
        }
        if (lane == 31) warpsum[wid] = xs;
        __syncthreads();
        if (wid == 0) {
            int w = warpsum[lane];
#pragma unroll
            for (int off = 1; off < 32; off <<= 1) {
                int t = __shfl_up_sync(0xffffffff, w, off);
                if (lane >= off) w += t;
            }
            warpsum[lane] = w;
        }
        __syncthreads();
        int wpre = (wid > 0) ? warpsum[wid - 1] : 0;
        int incl = xs + wpre;
        int excl = incl - v + carry;
        if (i < NN) { g_rowstart[i] = excl; g_cursor[i] = excl; }
        __syncthreads();
        if (threadIdx.x == 1023) carry += incl;
        __syncthreads();
    }
    if (threadIdx.x == 0) g_rowstart[NN] = carry;
}

__global__ void fill_kernel(const int* __restrict__ ei,
                            const int* __restrict__ ea) {
    int e = blockIdx.x * blockDim.x + threadIdx.x;
    if (e >= NE) return;
    int dst = ei[NE + e];
    int pos = atomicAdd(&g_cursor[dst], 1);
    int cb = ea[2 * e] * 4 + ea[2 * e + 1];
    g_edges[pos] = ei[e] | (cb << 16);
}

// ---------------- edge-combo tables for ALL layers ------------------------------
__global__ void eec_kernel(const float* __restrict__ e1,
                           const float* __restrict__ e2) {
    int b = blockIdx.x;            // 0..119 = l*24+cb
    int l = b / 24, cb = b % 24;
    int lane = threadIdx.x;
    int a0 = cb >> 2, a1 = cb & 3;
    float4 v1 = ((const float4*)(e1 + (size_t)l * 6 * D + (size_t)a0 * D))[lane];
    float4 v2 = ((const float4*)(e2 + (size_t)l * 4 * D + (size_t)a1 * D))[lane];
    ((float4*)g_eec)[(l * 24 + cb) * 32 + lane] =
        make_float4(v1.x + v2.x, v1.y + v2.y, v1.z + v2.z, v1.w + v2.w);
}

// ---------------- zero stats (once at prep; bnprep re-zeros per layer) ----------
__global__ void zero_stats_kernel() {
    g_sum[threadIdx.x] = 0.f;
    g_sumsq[threadIdx.x] = 0.f;
}

// ---------------- gather-aggregate: warp per node, emits bf16 hi/lo -------------
__global__ void agg_kernel(const float* __restrict__ h, int layer) {
    int t = blockIdx.x * blockDim.x + threadIdx.x;
    int n = t >> 5, lane = t & 31;
    if (n >= NN) return;
    const float4* eec = ((const float4*)g_eec) + layer * 24 * 32;
    int beg = g_rowstart[n], end = g_rowstart[n + 1];
    float4 acc = make_float4(0.f, 0.f, 0.f, 0.f);
    int i = beg;
    for (; i + 3 < end; i += 4) {
        int p0 = g_edges[i];
        int p1 = g_edges[i + 1];
        int p2 = g_edges[i + 2];
        int p3 = g_edges[i + 3];
        float4 a0 = ((const float4*)h)[(size_t)(p0 & 0xFFFF) * 32 + lane];
        float4 a1 = ((const float4*)h)[(size_t)(p1 & 0xFFFF) * 32 + lane];
        float4 a2 = ((const float4*)h)[(size_t)(p2 & 0xFFFF) * 32 + lane];
        float4 a3 = ((const float4*)h)[(size_t)(p3 & 0xFFFF) * 32 + lane];
        float4 e0 = eec[(p0 >> 16) * 32 + lane];
        float4 e1v = eec[(p1 >> 16) * 32 + lane];
        float4 e2v = eec[(p2 >> 16) * 32 + lane];
        float4 e3v = eec[(p3 >> 16) * 32 + lane];
        acc.x += (a0.x + e0.x) + (a1.x + e1v.x) + (a2.x + e2v.x) + (a3.x + e3v.x);
        acc.y += (a0.y + e0.y) + (a1.y + e1v.y) + (a2.y + e2v.y) + (a3.y + e3v.y);
        acc.z += (a0.z + e0.z) + (a1.z + e1v.z) + (a2.z + e2v.z) + (a3.z + e3v.z);
        acc.w += (a0.w + e0.w) + (a1.w + e1v.w) + (a2.w + e2v.w) + (a3.w + e3v.w);
    }
    for (; i < end; ++i) {
        int p0 = g_edges[i];
        float4 a = ((const float4*)h)[(size_t)(p0 & 0xFFFF) * 32 + lane];
        float4 e0 = eec[(p0 >> 16) * 32 + lane];
        acc.x += a.x + e0.x;
        acc.y += a.y + e0.y;
        acc.z += a.z + e0.z;
        acc.w += a.w + e0.w;
    }
    uint32_t h0, l0, h1, l1;
    split2(acc.x, acc.y, h0, l0);
    split2(acc.z, acc.w, h1, l1);
    ((uint2*)g_agg_hi)[(size_t)n * 32 + lane] = make_uint2(h0, h1);
    ((uint2*)g_agg_lo)[(size_t)n * 32 + lane] = make_uint2(l0, l1);
}

// ---------------- BN prep (also re-zeros stats for next layer) ------------------
__global__ void bnprep_kernel(const float* __restrict__ gamma,
                              const float* __restrict__ beta) {
    int c = threadIdx.x;
    const float inv = 1.0f / (float)NN;
    float mean = g_sum[c] * inv;
    float var = g_sumsq[c] * inv - mean * mean;
    float s = gamma[c] * rsqrtf(var + BN_EPS);
    g_bns[c] = s;
    g_bnt[c] = beta[c] - mean * s;
    g_sum[c] = 0.f;
    g_sumsq[c] = 0.f;
}

__global__ void bn_apply_kernel(const float* __restrict__ h2,
                                float* __restrict__ outp, int relu) {
    int t = blockIdx.x * blockDim.x + threadIdx.x;
    int node = t >> 5, lane = t & 31;
    if (node >= NN) return;
    float4 s4 = ((const float4*)g_bns)[lane];
    float4 t4 = ((const float4*)g_bnt)[lane];
    float4 v = ((const float4*)h2)[(size_t)node * 32 + lane];
    float4 o = make_float4(fmaf(s4.x, v.x, t4.x), fmaf(s4.y, v.y, t4.y),
                           fmaf(s4.z, v.z, t4.z), fmaf(s4.w, v.w, t4.w));
    if (relu) {
        o.x = fmaxf(o.x, 0.f); o.y = fmaxf(o.y, 0.f);
        o.z = fmaxf(o.z, 0.f); o.w = fmaxf(o.w, 0.f);
    }
    ((float4*)outp)[(size_t)node * 32 + lane] = o;
}

// ---------------- fused MLP: GEMM1 (relu) -> smem mid -> GEMM2 (+stats) ---------
#define MMA_BF16(acc, a, b)                                              \
    asm volatile(                                                        \
        "mma.sync.aligned.m16n8k16.row.col.f32.bf16.bf16.f32 "           \
        "{%0,%1,%2,%3}, {%4,%5,%6,%7}, {%8,%9}, {%0,%1,%2,%3};\n"        \
        : "+f"(acc[0]), "+f"(acc[1]), "+f"(acc[2]), "+f"(acc[3])         \
        : "r"(a[0]), "r"(a[1]), "r"(a[2]), "r"(a[3]),                    \
          "r"(b[0]), "r"(b[1]))

#define BM 128
#define N1 256
#define K1 128
#define N2 128
#define K2 256
#define APAD 136                         // bf16/row for A tile
#define MPAD 264                         // bf16/row for mid tile
#define WPAD 24                          // bf16/row for W chunks
#define MID_E (BM * MPAD)                // 33792 elems per type
#define SM_MID (2 * MID_E)               // 67584 elems
#define WBUF_E (N1 * WPAD * 2)           // 12288 elems (H+L) per buffer
#define SM_TOTAL_E (SM_MID + 2 * WBUF_E) // 92160 elems
#define SM_TOTAL_B (SM_TOTAL_E * 2)      // 184320 bytes

__global__ __launch_bounds__(256) void fused_mlp_kernel(
    const __nv_bfloat16* __restrict__ Ah, const __nv_bfloat16* __restrict__ Al,
    const __nv_bfloat16* __restrict__ W1h, const __nv_bfloat16* __restrict__ W1l,
    const float* __restrict__ b1,
    const __nv_bfloat16* __restrict__ W2h, const __nv_bfloat16* __restrict__ W2l,
    const float* __restrict__ b2,
    float* __restrict__ Cf) {
    extern __shared__ __nv_bfloat16 sm[];
    __nv_bfloat16* AsH = sm;                    // aliases mid region
    __nv_bfloat16* AsL = sm + BM * APAD;
    __nv_bfloat16* midH = sm;
    __nv_bfloat16* midL = sm + MID_E;

    const int tid  = threadIdx.x;
    const int warp = tid >> 5, lane = tid & 31;
    const int gid  = lane >> 2;
    const int tig  = lane & 3;
    const int wm   = (warp & 3) * 32;
    const int wn1  = (warp >> 2) * 128;
    const int wn2  = (warp >> 2) * 64;
    const int m0   = blockIdx.x * BM;

    // ---- stage full A tile (agg hi/lo) ----
#pragma unroll
    for (int t = 0; t < 8; t++) {
        int flat = t * 256 + tid;
        int row = flat >> 4, seg = flat & 15;
        bool ok = (m0 + row < NN);
        const __nv_bfloat16* s1 = ok ? Ah + (size_t)(m0 + row) * K1 + seg * 8 : Ah;
        const __nv_bfloat16* s2 = ok ? Al + (size_t)(m0 + row) * K1 + seg * 8 : Al;
        cp_async16(&AsH[row * APAD + seg * 8], s1, ok ? 16 : 0);
        cp_async16(&AsL[row * APAD + seg * 8], s2, ok ? 16 : 0);
    }

    auto stageW1 = [&](int c) {
        __nv_bfloat16* wb = sm + SM_MID + (c & 1) * WBUF_E;
        int n = tid;  // 0..255
        const __nv_bfloat16* sh = W1h + (size_t)n * K1 + c * 16;
        const __nv_bfloat16* sl = W1l + (size_t)n * K1 + c * 16;
        cp_async16(&wb[n * WPAD + 0], sh, 16);
        cp_async16(&wb[n * WPAD + 8], sh + 8, 16);
        cp_async16(&wb[N1 * WPAD + n * WPAD + 0], sl, 16);
        cp_async16(&wb[N1 * WPAD + n * WPAD + 8], sl + 8, 16);
        CP_COMMIT();
    };
    auto stageW2 = [&](int c) {
        __nv_bfloat16* wb = sm + SM_MID + (c & 1) * WBUF_E;
        int n = tid >> 1, seg = tid & 1;
        const __nv_bfloat16* sh = W2h + (size_t)n * K2 + c * 16 + seg * 8;
        const __nv_bfloat16* sl = W2l + (size_t)n * K2 + c * 16 + seg * 8;
        cp_async16(&wb[n * WPAD + seg * 8], sh, 16);
        cp_async16(&wb[N2 * WPAD + n * WPAD + seg * 8], sl, 16);
        CP_COMMIT();
    };

    stageW1(0);   // commits one group containing A copies + W1 chunk 0

    // ================= GEMM1: mid = relu(A @ W1^T + b1) =================
    float acc1[2][16][4];
#pragma unroll
    for (int mi = 0; mi < 2; mi++)
#pragma unroll
        for (int ni = 0; ni < 16; ni++)
#pragma unroll
            for (int q = 0; q < 4; q++) acc1[mi][ni][q] = 0.f;

    for (int c = 0; c < K1 / 16; c++) {
        if (c + 1 < K1 / 16) { stageW1(c + 1); CP_WAIT(1); }
        else                 { CP_WAIT(0); }
        __syncthreads();
        const __nv_bfloat16* wb = sm + SM_MID + (c & 1) * WBUF_E;
        const __nv_bfloat16* WH = wb;
        const __nv_bfloat16* WL = wb + N1 * WPAD;

        uint32_t ahf[2][4], alf[2][4];
#pragma unroll
        for (int mi = 0; mi < 2; mi++) {
            int r0 = wm + mi * 16 + gid;
            int kb = c * 16 + tig * 2;
            ahf[mi][0] = *(const uint32_t*)&AsH[r0 * APAD + kb];
            ahf[mi][1] = *(const uint32_t*)&AsH[(r0 + 8) * APAD + kb];
            ahf[mi][2] = *(const uint32_t*)&AsH[r0 * APAD + kb + 8];
            ahf[mi][3] = *(const uint32_t*)&AsH[(r0 + 8) * APAD + kb + 8];
            alf[mi][0] = *(const uint32_t*)&AsL[r0 * APAD + kb];
            alf[mi][1] = *(const uint32_t*)&AsL[(r0 + 8) * APAD + kb];
            alf[mi][2] = *(const uint32_t*)&AsL[r0 * APAD + kb + 8];
            alf[mi][3] = *(const uint32_t*)&AsL[(r0 + 8) * APAD + kb + 8];
        }
#pragma unroll
        for (int ni = 0; ni < 16; ni++) {
            int c0 = wn1 + ni * 8 + gid;
            uint32_t bh[2], bl[2];
            bh[0] = *(const uint32_t*)&WH[c0 * WPAD + tig * 2];
            bh[1] = *(const uint32_t*)&WH[c0 * WPAD + 8 + tig * 2];
            bl[0] = *(const uint32_t*)&WL[c0 * WPAD + tig * 2];
            bl[1] = *(const uint32_t*)&WL[c0 * WPAD + 8 + tig * 2];
#pragma unroll
            for (int mi = 0; mi < 2; mi++) {
                MMA_BF16(acc1[mi][ni], alf[mi], bh);
                MMA_BF16(acc1[mi][ni], ahf[mi], bl);
                MMA_BF16(acc1[mi][ni], ahf[mi], bh);
            }
        }
        __syncthreads();
    }

    // ---- epilogue1: bias+relu+split -> mid in smem (A region now dead) ----
#pragma unroll
    for (int mi = 0; mi < 2; mi++) {
        int r0 = wm + mi * 16 + gid;
#pragma unroll
        for (int ni = 0; ni < 16; ni++) {
            int n = wn1 + ni * 8 + tig * 2;
            float bv0 = b1[n], bv1 = b1[n + 1];
            float v0 = fmaxf(acc1[mi][ni][0] + bv0, 0.f);
            float v1 = fmaxf(acc1[mi][ni][1] + bv1, 0.f);
            float v2 = fmaxf(acc1[mi][ni][2] + bv0, 0.f);
            float v3 = fmaxf(acc1[mi][ni][3] + bv1, 0.f);
            uint32_t h0, l0, h1, l1;
            split2(v0, v1, h0, l0);
            split2(v2, v3, h1, l1);
            *(uint32_t*)&midH[r0 * MPAD + n] = h0;
            *(uint32_t*)&midL[r0 * MPAD + n] = l0;
            *(uint32_t*)&midH[(r0 + 8) * MPAD + n] = h1;
            *(uint32_t*)&midL[(r0 + 8) * MPAD + n] = l1;
        }
    }
    stageW2(0);
    __syncthreads();

    // ================= GEMM2: h2 = mid @ W2^T + b2 (+stats) =================
    float acc2[2][8][4];
#pragma unroll
    for (int mi = 0; mi < 2; mi++)
#pragma unroll
        for (int ni = 0; ni < 8; ni++)
#pragma unroll
            for (int q = 0; q < 4; q++) acc2[mi][ni][q] = 0.f;

    for (int c = 0; c < K2 / 16; c++) {
        if (c + 1 < K2 / 16) { stageW2(c + 1); CP_WAIT(1); }
        else                 { CP_WAIT(0); }
        __syncthreads();
        const __nv_bfloat16* wb = sm + SM_MID + (c & 1) * WBUF_E;
        const __nv_bfloat16* WH = wb;
        const __nv_bfloat16* WL = wb + N2 * WPAD;

        uint32_t ahf[2][4], alf[2][4];
#pragma unroll
        for (int mi = 0; mi < 2; mi++) {
            int r0 = wm + mi * 16 + gid;
            int kb = c * 16 + tig * 2;
            ahf[mi][0] = *(const uint32_t*)&midH[r0 * MPAD + kb];
            ahf[mi][1] = *(const uint32_t*)&midH[(r0 + 8) * MPAD + kb];
            ahf[mi][2] = *(const uint32_t*)&midH[r0 * MPAD + kb + 8];
            ahf[mi][3] = *(const uint32_t*)&midH[(r0 + 8) * MPAD + kb + 8];
            alf[mi][0] = *(const uint32_t*)&midL[r0 * MPAD + kb];
            alf[mi][1] = *(const uint32_t*)&midL[(r0 + 8) * MPAD + kb];
            alf[mi][2] = *(const uint32_t*)&midL[r0 * MPAD + kb + 8];
            alf[mi][3] = *(const uint32_t*)&midL[(r0 + 8) * MPAD + kb + 8];
        }
#pragma unroll
        for (int ni = 0; ni < 8; ni++) {
            int c0 = wn2 + ni * 8 + gid;
            uint32_t bh[2], bl[2];
            bh[0] = *(const uint32_t*)&WH[c0 * WPAD + tig * 2];
            bh[1] = *(const uint32_t*)&WH[c0 * WPAD + 8 + tig * 2];
            bl[0] = *(const uint32_t*)&WL[c0 * WPAD + tig * 2];
            bl[1] = *(const uint32_t*)&WL[c0 * WPAD + 8 + tig * 2];
#pragma unroll
            for (int mi = 0; mi < 2; mi++) {
                MMA_BF16(acc2[mi][ni], alf[mi], bh);
                MMA_BF16(acc2[mi][ni], ahf[mi], bl);
                MMA_BF16(acc2[mi][ni], ahf[mi], bh);
            }
        }
        __syncthreads();
    }

    // ---- epilogue2: bias, fp32 store, fused column stats ----
    float ls[16], ls2[16];
#pragma unroll
    for (int j = 0; j < 16; j++) { ls[j] = 0.f; ls2[j] = 0.f; }

#pragma unroll
    for (int mi = 0; mi < 2; mi++) {
        int r0 = m0 + wm + mi * 16 + gid;
#pragma unroll
        for (int ni = 0; ni < 8; ni++) {
            int gc = wn2 + ni * 8 + 2 * tig;
            float bv0 = b2[gc], bv1 = b2[gc + 1];
            float v0 = acc2[mi][ni][0] + bv0;
            float v1 = acc2[mi][ni][1] + bv1;
            float v2 = acc2[mi][ni][2] + bv0;
            float v3 = acc2[mi][ni][3] + bv1;
            bool ok0 = (r0 < NN), ok1 = (r0 + 8 < NN);
            if (ok0) {
                *(float2*)(Cf + (size_t)r0 * N2 + gc) = make_float2(v0, v1);
                ls[ni * 2]     += v0; ls2[ni * 2]     += v0 * v0;
                ls[ni * 2 + 1] += v1; ls2[ni * 2 + 1] += v1 * v1;
            }
            if (ok1) {
                *(float2*)(Cf + (size_t)(r0 + 8) * N2 + gc) = make_float2(v2, v3);
                ls[ni * 2]     += v2; ls2[ni * 2]     += v2 * v2;
                ls[ni * 2 + 1] += v3; ls2[ni * 2 + 1] += v3 * v3;
            }
        }
    }

#pragma unroll
    for (int j = 0; j < 16; j++) {
#pragma unroll
        for (int off = 4; off < 32; off <<= 1) {
            ls[j]  += __shfl_xor_sync(0xffffffff, ls[j], off);
            ls2[j] += __shfl_xor_sync(0xffffffff, ls2[j], off);
        }
    }
    float* cs  = (float*)sm;      // mid region dead after last chunk's sync
    float* cs2 = (float*)sm + 128;
    if (tid < 128) { cs[tid] = 0.f; cs2[tid] = 0.f; }
    __syncthreads();
    if (lane < 4) {
#pragma unroll
        for (int ni = 0; ni < 8; ni++) {
            int c0 = wn2 + ni * 8 + 2 * lane;
            atomicAdd(&cs[c0],      ls[ni * 2]);
            atomicAdd(&cs2[c0],     ls2[ni * 2]);
            atomicAdd(&cs[c0 + 1],  ls[ni * 2 + 1]);
            atomicAdd(&cs2[c0 + 1], ls2[ni * 2 + 1]);
        }
    }
    __syncthreads();
    if (tid < 128) {
        atomicAdd(&g_sum[tid],   cs[tid]);
        atomicAdd(&g_sumsq[tid], cs2[tid]);
    }
}

// ---------------- launch --------------------------------------------------------
extern "C" void kernel_launch(void* const* d_in, const int* in_sizes, int n_in,
                              void* d_out, int out_size) {
    const int*   x     = (const int*)d_in[0];
    const int*   ei    = (const int*)d_in[1];
    const int*   ea    = (const int*)d_in[2];
    const float* atom  = (const float*)d_in[3];
    const float* chir  = (const float*)d_in[4];
    const float* hyb   = (const float*)d_in[5];
    const float* e1    = (const float*)d_in[6];
    const float* e2    = (const float*)d_in[7];
    const float* W1    = (const float*)d_in[8];
    const float* b1    = (const float*)d_in[9];
    const float* W2    = (const float*)d_in[10];
    const float* b2    = (const float*)d_in[11];
    const float* gamma = (const float*)d_in[12];
    const float* beta  = (const float*)d_in[13];
    float* out = (float*)d_out;

    float *p_h, *p_h2;
    int* p_cnt;
    __nv_bfloat16 *p_agg_hi, *p_agg_lo;
    __nv_bfloat16 *p_wt1_hi, *p_wt1_lo, *p_wt2_hi, *p_wt2_lo;
    cudaGetSymbolAddress((void**)&p_h,      g_h);
    cudaGetSymbolAddress((void**)&p_h2,     g_h2);
    cudaGetSymbolAddress((void**)&p_cnt,    g_cnt);
    cudaGetSymbolAddress((void**)&p_agg_hi, g_agg_hi);
    cudaGetSymbolAddress((void**)&p_agg_lo, g_agg_lo);
    cudaGetSymbolAddress((void**)&p_wt1_hi, g_wt1_hi);
    cudaGetSymbolAddress((void**)&p_wt1_lo, g_wt1_lo);
    cudaGetSymbolAddress((void**)&p_wt2_hi, g_wt2_hi);
    cudaGetSymbolAddress((void**)&p_wt2_lo, g_wt2_lo);

    cudaFuncSetAttribute(fused_mlp_kernel,
                         cudaFuncAttributeMaxDynamicSharedMemorySize,
                         SM_TOTAL_B);

    const int TPB = 256;
    const int node_blocks = (NN * 32 + TPB - 1) / TPB;
    const int edge_blocks = (NE + TPB - 1) / TPB;
    const int mrows = (NN + BM - 1) / BM;

    // one-time prep (layer-invariant)
    cudaMemsetAsync(p_cnt, 0, NN * sizeof(int));
    zero_stats_kernel<<<1, 128>>>();
    count_kernel<<<edge_blocks, TPB>>>(ei);
    scan_kernel<<<1, 1024>>>();
    fill_kernel<<<edge_blocks, TPB>>>(ei, ea);
    wprep_kernel<<<(2 * 5 * 128 * 256 + TPB - 1) / TPB, TPB>>>(W1, W2);
    eec_kernel<<<120, 32>>>(e1, e2);
    embed_kernel<<<node_blocks, TPB>>>(x, atom, chir, hyb);

    for (int l = 0; l < 5; ++l) {
        agg_kernel<<<node_blocks, TPB>>>(p_h, l);
        fused_mlp_kernel<<<mrows, 256, SM_TOTAL_B>>>(
            p_agg_hi, p_agg_lo,
            p_wt1_hi + (size_t)l * 32768, p_wt1_lo + (size_t)l * 32768,
            b1 + (size_t)l * 2 * D,
            p_wt2_hi + (size_t)l * 32768, p_wt2_lo + (size_t)l * 32768,
            b2 + (size_t)l * D,
            p_h2);
        bnprep_kernel<<<1, 128>>>(gamma + (size_t)l * D, beta + (size_t)l * D);
        bn_apply_kernel<<<node_blocks, TPB>>>(p_h2, (l == 4) ? out : p_h,
                                              (l < 4) ? 1 : 0);
    }
}

// round 11
// speedup vs baseline: 1.0332x; 1.0332x over previous
#include <cuda_runtime.h>
#include <cuda_bf16.h>
#include <cstdint>
#include <cstddef>

#define NN 50000
#define NE 600000
#define D 128
#define BN_EPS 1e-5f

// ---------------- scratch (device globals) -------------------------------------
__device__ float g_h[NN * D];                 // post-BN node features (fp32)
__device__ __nv_bfloat16 g_agg_hi[NN * D];    // aggregate, bf16 split
__device__ __nv_bfloat16 g_agg_lo[NN * D];
__device__ __nv_bfloat16 g_mid_hi[NN * 2 * D];
__device__ __nv_bfloat16 g_mid_lo[NN * 2 * D];
__device__ float g_h2[NN * D];                // pre-BN layer output (fp32)
__device__ float g_sum[D];
__device__ float g_sumsq[D];
__device__ float g_bns[D];
__device__ float g_bnt[D];
// pre-split transposed weights
__device__ __nv_bfloat16 g_wt1_hi[5 * 256 * 128];
__device__ __nv_bfloat16 g_wt1_lo[5 * 256 * 128];
__device__ __nv_bfloat16 g_wt2_hi[5 * 128 * 256];
__device__ __nv_bfloat16 g_wt2_lo[5 * 128 * 256];
// CSR structures
__device__ int   g_cnt[NN];
__device__ int   g_rowstart[NN + 1];
__device__ int   g_cursor[NN];
__device__ int   g_edges[NE];                 // src | (combo << 16)
__device__ float g_eec[5 * 24 * D];           // all layers precomputed

// ---------------- helpers -------------------------------------------------------
__device__ __forceinline__ uint32_t pack2bf(float x, float y) {
    __nv_bfloat162 h = __floats2bfloat162_rn(x, y);
    return *(uint32_t*)&h;
}
__device__ __forceinline__ void split2(float x, float y,
                                       uint32_t& hi, uint32_t& lo) {
    __nv_bfloat16 hx = __float2bfloat16(x);
    __nv_bfloat16 hy = __float2bfloat16(y);
    float rx = x - __bfloat162float(hx);
    float ry = y - __bfloat162float(hy);
    __nv_bfloat162 h2 = __halves2bfloat162(hx, hy);
    hi = *(uint32_t*)&h2;
    lo = pack2bf(rx, ry);
}
__device__ __forceinline__ void cp_async16(void* dst, const void* src,
                                           int src_bytes) {
    uint32_t d = (uint32_t)__cvta_generic_to_shared(dst);
    asm volatile("cp.async.cg.shared.global [%0], [%1], 16, %2;\n"
                 :: "r"(d), "l"(src), "r"(src_bytes));
}
#define CP_COMMIT() asm volatile("cp.async.commit_group;\n" ::: "memory")
#define CP_WAIT(n)  asm volatile("cp.async.wait_group %0;\n" :: "n"(n) : "memory")

#define LDSM4(r, addr)                                                    \
    asm volatile("ldmatrix.sync.aligned.m8n8.x4.shared.b16 "              \
                 "{%0,%1,%2,%3}, [%4];"                                   \
                 : "=r"((r)[0]), "=r"((r)[1]), "=r"((r)[2]), "=r"((r)[3]) \
                 : "r"(addr))

// ---------------- input embedding ---------------------------------------------
__global__ void embed_kernel(const int* __restrict__ x,
                             const float* __restrict__ atom,
                             const float* __restrict__ chir,
                             const float* __restrict__ hyb) {
    int t = blockIdx.x * blockDim.x + threadIdx.x;
    int node = t >> 5, lane = t & 31;
    if (node >= NN) return;
    int x0 = x[node * 3 + 0];
    int x1 = x[node * 3 + 1];
    int x2 = x[node * 3 + 2];
    float4 a = ((const float4*)(atom + (size_t)x0 * D))[lane];
    float4 c = ((const float4*)(chir + (size_t)x1 * D))[lane];
    float4 y = ((const float4*)(hyb  + (size_t)x2 * D))[lane];
    ((float4*)g_h)[(size_t)node * 32 + lane] =
        make_float4(a.x + c.x + y.x, a.y + c.y + y.y,
                    a.z + c.z + y.z, a.w + c.w + y.w);
}

// ---------------- weight prep: transpose + bf16 split --------------------------
__global__ void wprep_kernel(const float* __restrict__ W1,
                             const float* __restrict__ W2) {
    int t = blockIdx.x * blockDim.x + threadIdx.x;
    int total = 5 * 128 * 256;
    if (t < total) {
        int l = t / (128 * 256);
        int r = t % (128 * 256);
        int k = r / 256, n = r % 256;
        float v = W1[t];
        __nv_bfloat16 h = __float2bfloat16(v);
        g_wt1_hi[l * 32768 + n * 128 + k] = h;
        g_wt1_lo[l * 32768 + n * 128 + k] =
            __float2bfloat16(v - __bfloat162float(h));
    } else if (t < 2 * total) {
        int u = t - total;
        int l = u / (256 * 128);
        int r = u % (256 * 128);
        int k = r / 128, n = r % 128;
        float v = W2[u];
        __nv_bfloat16 h = __float2bfloat16(v);
        g_wt2_hi[l * 32768 + n * 256 + k] = h;
        g_wt2_lo[l * 32768 + n * 256 + k] =
            __float2bfloat16(v - __bfloat162float(h));
    }
}

// ---------------- CSR build ----------------------------------------------------
__global__ void count_kernel(const int* __restrict__ ei) {
    int e = blockIdx.x * blockDim.x + threadIdx.x;
    if (e >= NE) return;
    atomicAdd(&g_cnt[ei[NE + e]], 1);
}

__global__ void scan_kernel() {
    __shared__ int warpsum[32];
    __shared__ int carry;
    int lane = threadIdx.x & 31, wid = threadIdx.x >> 5;
    if (threadIdx.x == 0) carry = 0;
    __syncthreads();
    for (int base = 0; base < NN; base += 1024) {
        int i = base + threadIdx.x;
        int v = (i < NN) ? g_cnt[i] : 0;
        int xs = v;
#pragma unroll
        for (int off = 1; off < 32; off <<= 1) {
            int t = __shfl_up_sync(0xffffffff, xs, off);
            if (lane >= off) xs += t;
        }
        if (lane == 31) warpsum[wid] = xs;
        __syncthreads();
        if (wid == 0) {
            int w = warpsum[lane];
#pragma unroll
            for (int off = 1; off < 32; off <<= 1) {
                int t = __shfl_up_sync(0xffffffff, w, off);
                if (lane >= off) w += t;
            }
            warpsum[lane] = w;
        }
        __syncthreads();
        int wpre = (wid > 0) ? warpsum[wid - 1] : 0;
        int incl = xs + wpre;
        int excl = incl - v + carry;
        if (i < NN) { g_rowstart[i] = excl; g_cursor[i] = excl; }
        __syncthreads();
        if (threadIdx.x == 1023) carry += incl;
        __syncthreads();
    }
    if (threadIdx.x == 0) g_rowstart[NN] = carry;
}

__global__ void fill_kernel(const int* __restrict__ ei,
                            const int* __restrict__ ea) {
    int e = blockIdx.x * blockDim.x + threadIdx.x;
    if (e >= NE) return;
    int dst = ei[NE + e];
    int pos = atomicAdd(&g_cursor[dst], 1);
    int cb = ea[2 * e] * 4 + ea[2 * e + 1];
    g_edges[pos] = ei[e] | (cb << 16);
}

// ---------------- edge-combo tables for ALL layers ------------------------------
__global__ void eec_kernel(const float* __restrict__ e1,
                           const float* __restrict__ e2) {
    int b = blockIdx.x;            // 0..119 = l*24+cb
    int l = b / 24, cb = b % 24;
    int lane = threadIdx.x;
    int a0 = cb >> 2, a1 = cb & 3;
    float4 v1 = ((const float4*)(e1 + (size_t)l * 6 * D + (size_t)a0 * D))[lane];
    float4 v2 = ((const float4*)(e2 + (size_t)l * 4 * D + (size_t)a1 * D))[lane];
    ((float4*)g_eec)[(l * 24 + cb) * 32 + lane] =
        make_float4(v1.x + v2.x, v1.y + v2.y, v1.z + v2.z, v1.w + v2.w);
}

// ---------------- zero stats (once at prep; bnprep re-zeros per layer) ----------
__global__ void zero_stats_kernel() {
    g_sum[threadIdx.x] = 0.f;
    g_sumsq[threadIdx.x] = 0.f;
}

// ---------------- gather-aggregate: warp per node, emits bf16 hi/lo -------------
__global__ void agg_kernel(const float* __restrict__ h, int layer) {
    int t = blockIdx.x * blockDim.x + threadIdx.x;
    int n = t >> 5, lane = t & 31;
    if (n >= NN) return;
    const float4* eec = ((const float4*)g_eec) + layer * 24 * 32;
    int beg = g_rowstart[n], end = g_rowstart[n + 1];
    float4 acc = make_float4(0.f, 0.f, 0.f, 0.f);
    int i = beg;
    for (; i + 3 < end; i += 4) {
        int p0 = g_edges[i];
        int p1 = g_edges[i + 1];
        int p2 = g_edges[i + 2];
        int p3 = g_edges[i + 3];
        float4 a0 = ((const float4*)h)[(size_t)(p0 & 0xFFFF) * 32 + lane];
        float4 a1 = ((const float4*)h)[(size_t)(p1 & 0xFFFF) * 32 + lane];
        float4 a2 = ((const float4*)h)[(size_t)(p2 & 0xFFFF) * 32 + lane];
        float4 a3 = ((const float4*)h)[(size_t)(p3 & 0xFFFF) * 32 + lane];
        float4 e0 = eec[(p0 >> 16) * 32 + lane];
        float4 e1v = eec[(p1 >> 16) * 32 + lane];
        float4 e2v = eec[(p2 >> 16) * 32 + lane];
        float4 e3v = eec[(p3 >> 16) * 32 + lane];
        acc.x += (a0.x + e0.x) + (a1.x + e1v.x) + (a2.x + e2v.x) + (a3.x + e3v.x);
        acc.y += (a0.y + e0.y) + (a1.y + e1v.y) + (a2.y + e2v.y) + (a3.y + e3v.y);
        acc.z += (a0.z + e0.z) + (a1.z + e1v.z) + (a2.z + e2v.z) + (a3.z + e3v.z);
        acc.w += (a0.w + e0.w) + (a1.w + e1v.w) + (a2.w + e2v.w) + (a3.w + e3v.w);
    }
    for (; i < end; ++i) {
        int p0 = g_edges[i];
        float4 a = ((const float4*)h)[(size_t)(p0 & 0xFFFF) * 32 + lane];
        float4 e0 = eec[(p0 >> 16) * 32 + lane];
        acc.x += a.x + e0.x;
        acc.y += a.y + e0.y;
        acc.z += a.z + e0.z;
        acc.w += a.w + e0.w;
    }
    uint32_t h0, l0, h1, l1;
    split2(acc.x, acc.y, h0, l0);
    split2(acc.z, acc.w, h1, l1);
    ((uint2*)g_agg_hi)[(size_t)n * 32 + lane] = make_uint2(h0, h1);
    ((uint2*)g_agg_lo)[(size_t)n * 32 + lane] = make_uint2(l0, l1);
}

// ---------------- BN prep (also re-zeros stats for next layer) ------------------
__global__ void bnprep_kernel(const float* __restrict__ gamma,
                              const float* __restrict__ beta) {
    int c = threadIdx.x;
    const float inv = 1.0f / (float)NN;
    float mean = g_sum[c] * inv;
    float var = g_sumsq[c] * inv - mean * mean;
    float s = gamma[c] * rsqrtf(var + BN_EPS);
    g_bns[c] = s;
    g_bnt[c] = beta[c] - mean * s;
    g_sum[c] = 0.f;
    g_sumsq[c] = 0.f;
}

__global__ void bn_apply_kernel(const float* __restrict__ h2,
                                float* __restrict__ outp, int relu) {
    int t = blockIdx.x * blockDim.x + threadIdx.x;
    int node = t >> 5, lane = t & 31;
    if (node >= NN) return;
    float4 s4 = ((const float4*)g_bns)[lane];
    float4 t4 = ((const float4*)g_bnt)[lane];
    float4 v = ((const float4*)h2)[(size_t)node * 32 + lane];
    float4 o = make_float4(fmaf(s4.x, v.x, t4.x), fmaf(s4.y, v.y, t4.y),
                           fmaf(s4.z, v.z, t4.z), fmaf(s4.w, v.w, t4.w));
    if (relu) {
        o.x = fmaxf(o.x, 0.f); o.y = fmaxf(o.y, 0.f);
        o.z = fmaxf(o.z, 0.f); o.w = fmaxf(o.w, 0.f);
    }
    ((float4*)outp)[(size_t)node * 32 + lane] = o;
}

// ---------------- bf16x3 GEMM: cp.async double-buffered + ldmatrix --------------
#define MMA_BF16(acc, a, b)                                              \
    asm volatile(                                                        \
        "mma.sync.aligned.m16n8k16.row.col.f32.bf16.bf16.f32 "           \
        "{%0,%1,%2,%3}, {%4,%5,%6,%7}, {%8,%9}, {%0,%1,%2,%3};\n"        \
        : "+f"(acc[0]), "+f"(acc[1]), "+f"(acc[2]), "+f"(acc[3])         \
        : "r"(a[0]), "r"(a[1]), "r"(a[2]), "r"(a[3]),                    \
          "r"(b[0]), "r"(b[1]))

#define PAD 40
#define TILE_E (128 * PAD)              // bf16 elems per tile
#define TILE_B (TILE_E * 2)             // bytes per tile
#define STAGE_E (4 * TILE_E)            // 4 tiles per stage
#define SMEM_BYTES (2 * STAGE_E * 2)    // 2 stages = 81920 bytes

__global__ __launch_bounds__(256) void gemm_bf16x3_kernel(
    const __nv_bfloat16* __restrict__ Ah, const __nv_bfloat16* __restrict__ Al,
    const __nv_bfloat16* __restrict__ Bh, const __nv_bfloat16* __restrict__ Bl,
    const float* __restrict__ bias,
    float* __restrict__ Cf, __nv_bfloat16* __restrict__ Ch,
    __nv_bfloat16* __restrict__ Cl,
    int M, int N, int K, int relu, int do_stats, int out_bf16) {
    extern __shared__ __nv_bfloat16 smem[];

    const int tid  = threadIdx.x;
    const int warp = tid >> 5, lane = tid & 31;
    const int gid  = lane >> 2;
    const int tig  = lane & 3;
    const int wm   = (warp & 3) * 32;
    const int wn   = (warp >> 2) * 64;
    const int m0   = blockIdx.y * 128;
    const int n0b  = blockIdx.x * 128;

    float acc[2][8][4];
#pragma unroll
    for (int mi = 0; mi < 2; mi++)
#pragma unroll
        for (int ni = 0; ni < 8; ni++)
#pragma unroll
            for (int q = 0; q < 4; q++) acc[mi][ni][q] = 0.f;

    const int sr = tid >> 2;            // 0..63
    const int sc = (tid & 3) * 8;       // 16B = 8 bf16

    const int nchunk = K >> 5;          // BK=32

    // per-lane ldmatrix byte offsets (within a tile)
    uint32_t offA[2];
#pragma unroll
    for (int mi = 0; mi < 2; mi++) {
        int row = wm + mi * 16 + (lane & 15);
        int cg  = lane >> 4;                  // 0/1 -> col 0/8
        offA[mi] = (uint32_t)(row * PAD + cg * 8) * 2;
    }
    uint32_t offB[4];
#pragma unroll
    for (int nj = 0; nj < 4; nj++) {
        int row = wn + nj * 16 + ((lane >> 4) * 8) + (lane & 7);
        int cg  = (lane >> 3) & 1;
        offB[nj] = (uint32_t)(row * PAD + cg * 8) * 2;
    }
    const uint32_t smem_u32 = (uint32_t)__cvta_generic_to_shared(smem);

    auto stage = [&](int c) {
        __nv_bfloat16* buf = smem + (c & 1) * STAGE_E;
        __nv_bfloat16* Ah_s = buf;
        __nv_bfloat16* Al_s = buf + TILE_E;
        __nv_bfloat16* Bh_s = buf + 2 * TILE_E;
        __nv_bfloat16* Bl_s = buf + 3 * TILE_E;
        int k0 = c << 5;
#pragma unroll
        for (int i = 0; i < 2; i++) {
            int r = sr + i * 64;
            bool ok = (m0 + r < M);
            const __nv_bfloat16* sa = ok ? (Ah + (size_t)(m0 + r) * K + k0 + sc) : Ah;
            const __nv_bfloat16* sl = ok ? (Al + (size_t)(m0 + r) * K + k0 + sc) : Al;
            cp_async16(&Ah_s[r * PAD + sc], sa, ok ? 16 : 0);
            cp_async16(&Al_s[r * PAD + sc], sl, ok ? 16 : 0);
            cp_async16(&Bh_s[r * PAD + sc], Bh + (size_t)(n0b + r) * K + k0 + sc, 16);
            cp_async16(&Bl_s[r * PAD + sc], Bl + (size_t)(n0b + r) * K + k0 + sc, 16);
        }
        CP_COMMIT();
    };

    stage(0);

    for (int c = 0; c < nchunk; ++c) {
        if (c + 1 < nchunk) {
            stage(c + 1);
            CP_WAIT(1);
        } else {
            CP_WAIT(0);
        }
        __syncthreads();

        uint32_t sb = smem_u32 + (uint32_t)((c & 1) * STAGE_E * 2);

#pragma unroll
        for (int ks = 0; ks < 2; ks++) {
            const uint32_t kb = ks * 32;   // 16 bf16 = 32 bytes
            uint32_t ah[2][4], al[2][4];
            LDSM4(ah[0], sb + offA[0] + kb);
            LDSM4(ah[1], sb + offA[1] + kb);
            LDSM4(al[0], sb + TILE_B + offA[0] + kb);
            LDSM4(al[1], sb + TILE_B + offA[1] + kb);
            uint32_t bh[8][2], bl[8][2];
#pragma unroll
            for (int nj = 0; nj < 4; nj++) {
                uint32_t th[4], tl[4];
                LDSM4(th, sb + 2 * TILE_B + offB[nj] + kb);
                LDSM4(tl, sb + 3 * TILE_B + offB[nj] + kb);
                bh[2 * nj][0] = th[0]; bh[2 * nj][1] = th[1];
                bh[2 * nj + 1][0] = th[2]; bh[2 * nj + 1][1] = th[3];
                bl[2 * nj][0] = tl[0]; bl[2 * nj][1] = tl[1];
                bl[2 * nj + 1][0] = tl[2]; bl[2 * nj + 1][1] = tl[3];
            }
#pragma unroll
            for (int mi = 0; mi < 2; mi++)
#pragma unroll
                for (int ni = 0; ni < 8; ni++) {
                    MMA_BF16(acc[mi][ni], al[mi], bh[ni]);
                    MMA_BF16(acc[mi][ni], ah[mi], bl[ni]);
                    MMA_BF16(acc[mi][ni], ah[mi], bh[ni]);
                }
        }
        __syncthreads();
    }

    // epilogue
    float ls[16], ls2[16];
#pragma unroll
    for (int j = 0; j < 16; j++) { ls[j] = 0.f; ls2[j] = 0.f; }

#pragma unroll
    for (int mi = 0; mi < 2; mi++) {
        int r0 = m0 + wm + mi * 16 + gid;
#pragma unroll
        for (int ni = 0; ni < 8; ni++) {
            int gc = n0b + wn + ni * 8 + 2 * tig;
            float bv0 = bias[gc], bv1 = bias[gc + 1];
            float v0 = acc[mi][ni][0] + bv0;
            float v1 = acc[mi][ni][1] + bv1;
            float v2 = acc[mi][ni][2] + bv0;
            float v3 = acc[mi][ni][3] + bv1;
            if (relu) {
                v0 = fmaxf(v0, 0.f); v1 = fmaxf(v1, 0.f);
                v2 = fmaxf(v2, 0.f); v3 = fmaxf(v3, 0.f);
            }
            bool ok0 = (r0 < M), ok1 = (r0 + 8 < M);
            if (out_bf16) {
                uint32_t h0, l0, h1, l1;
                split2(v0, v1, h0, l0);
                split2(v2, v3, h1, l1);
                if (ok0) {
                    *(uint32_t*)(Ch + (size_t)r0 * N + gc) = h0;
                    *(uint32_t*)(Cl + (size_t)r0 * N + gc) = l0;
                }
                if (ok1) {
                    *(uint32_t*)(Ch + (size_t)(r0 + 8) * N + gc) = h1;
                    *(uint32_t*)(Cl + (size_t)(r0 + 8) * N + gc) = l1;
                }
            } else {
                if (ok0)
                    *(float2*)(Cf + (size_t)r0 * N + gc) = make_float2(v0, v1);
                if (ok1)
                    *(float2*)(Cf + (size_t)(r0 + 8) * N + gc) = make_float2(v2, v3);
            }
            if (do_stats) {
                if (ok0) {
                    ls[ni * 2]     += v0; ls2[ni * 2]     += v0 * v0;
                    ls[ni * 2 + 1] += v1; ls2[ni * 2 + 1] += v1 * v1;
                }
                if (ok1) {
                    ls[ni * 2]     += v2; ls2[ni * 2]     += v2 * v2;
                    ls[ni * 2 + 1] += v3; ls2[ni * 2 + 1] += v3 * v3;
                }
            }
        }
    }

    if (do_stats) {
#pragma unroll
        for (int j = 0; j < 16; j++) {
#pragma unroll
            for (int off = 4; off < 32; off <<= 1) {
                ls[j]  += __shfl_xor_sync(0xffffffff, ls[j], off);
                ls2[j] += __shfl_xor_sync(0xffffffff, ls2[j], off);
            }
        }
        float* cs  = (float*)smem;
        float* cs2 = (float*)smem + 128;
        if (tid < 128) { cs[tid] = 0.f; cs2[tid] = 0.f; }
        __syncthreads();
        if (lane < 4) {
#pragma unroll
            for (int ni = 0; ni < 8; ni++) {
                int c0 = wn + ni * 8 + 2 * lane;
                atomicAdd(&cs[c0],      ls[ni * 2]);
                atomicAdd(&cs2[c0],     ls2[ni * 2]);
                atomicAdd(&cs[c0 + 1],  ls[ni * 2 + 1]);
                atomicAdd(&cs2[c0 + 1], ls2[ni * 2 + 1]);
            }
        }
        __syncthreads();
        if (tid < 128) {
            atomicAdd(&g_sum[tid],   cs[tid]);
            atomicAdd(&g_sumsq[tid], cs2[tid]);
        }
    }
}

// ---------------- launch --------------------------------------------------------
extern "C" void kernel_launch(void* const* d_in, const int* in_sizes, int n_in,
                              void* d_out, int out_size) {
    const int*   x     = (const int*)d_in[0];
    const int*   ei    = (const int*)d_in[1];
    const int*   ea    = (const int*)d_in[2];
    const float* atom  = (const float*)d_in[3];
    const float* chir  = (const float*)d_in[4];
    const float* hyb   = (const float*)d_in[5];
    const float* e1    = (const float*)d_in[6];
    const float* e2    = (const float*)d_in[7];
    const float* W1    = (const float*)d_in[8];
    const float* b1    = (const float*)d_in[9];
    const float* W2    = (const float*)d_in[10];
    const float* b2    = (const float*)d_in[11];
    const float* gamma = (const float*)d_in[12];
    const float* beta  = (const float*)d_in[13];
    float* out = (float*)d_out;

    float *p_h, *p_h2;
    int* p_cnt;
    __nv_bfloat16 *p_agg_hi, *p_agg_lo, *p_mid_hi, *p_mid_lo;
    __nv_bfloat16 *p_wt1_hi, *p_wt1_lo, *p_wt2_hi, *p_wt2_lo;
    cudaGetSymbolAddress((void**)&p_h,      g_h);
    cudaGetSymbolAddress((void**)&p_h2,     g_h2);
    cudaGetSymbolAddress((void**)&p_cnt,    g_cnt);
    cudaGetSymbolAddress((void**)&p_agg_hi, g_agg_hi);
    cudaGetSymbolAddress((void**)&p_agg_lo, g_agg_lo);
    cudaGetSymbolAddress((void**)&p_mid_hi, g_mid_hi);
    cudaGetSymbolAddress((void**)&p_mid_lo, g_mid_lo);
    cudaGetSymbolAddress((void**)&p_wt1_hi, g_wt1_hi);
    cudaGetSymbolAddress((void**)&p_wt1_lo, g_wt1_lo);
    cudaGetSymbolAddress((void**)&p_wt2_hi, g_wt2_hi);
    cudaGetSymbolAddress((void**)&p_wt2_lo, g_wt2_lo);

    cudaFuncSetAttribute(gemm_bf16x3_kernel,
                         cudaFuncAttributeMaxDynamicSharedMemorySize,
                         SMEM_BYTES);

    const int TPB = 256;
    const int node_blocks = (NN * 32 + TPB - 1) / TPB;
    const int edge_blocks = (NE + TPB - 1) / TPB;
    const int mrows = (NN + 127) / 128;

    // one-time prep (layer-invariant)
    cudaMemsetAsync(p_cnt, 0, NN * sizeof(int));
    zero_stats_kernel<<<1, 128>>>();
    count_kernel<<<edge_blocks, TPB>>>(ei);
    scan_kernel<<<1, 1024>>>();
    fill_kernel<<<edge_blocks, TPB>>>(ei, ea);
    wprep_kernel<<<(2 * 5 * 128 * 256 + TPB - 1) / TPB, TPB>>>(W1, W2);
    eec_kernel<<<120, 32>>>(e1, e2);
    embed_kernel<<<node_blocks, TPB>>>(x, atom, chir, hyb);

    for (int l = 0; l < 5; ++l) {
        agg_kernel<<<node_blocks, TPB>>>(p_h, l);
        // Linear1 + ReLU -> mid (bf16 hi/lo)
        gemm_bf16x3_kernel<<<dim3(2, mrows), 256, SMEM_BYTES>>>(
            p_agg_hi, p_agg_lo,
            p_wt1_hi + (size_t)l * 32768, p_wt1_lo + (size_t)l * 32768,
            b1 + (size_t)l * 2 * D,
            nullptr, p_mid_hi, p_mid_lo,
            NN, 2 * D, D, 1, 0, 1);
        // Linear2 -> h2 (fp32) with fused column stats
        gemm_bf16x3_kernel<<<dim3(1, mrows), 256, SMEM_BYTES>>>(
            p_mid_hi, p_mid_lo,
            p_wt2_hi + (size_t)l * 32768, p_wt2_lo + (size_t)l * 32768,
            b2 + (size_t)l * D,
            p_h2, nullptr, nullptr,
            NN, D, 2 * D, 0, 1, 0);
        bnprep_kernel<<<1, 128>>>(gamma + (size_t)l * D, beta + (size_t)l * D);
        bn_apply_kernel<<<node_blocks, TPB>>>(p_h2, (l == 4) ? out : p_h,
                                              (l < 4) ? 1 : 0);
    }
}